// round 2
// baseline (speedup 1.0000x reference)
#include <cuda_runtime.h>
#include <cuda_bf16.h>

#define MATSIZE 512
#define DSZ 10
#define NR (MATSIZE - 2 * DSZ)          // 492 outputs per batch
#define TSPLIT 2
#define TPB (NR / TSPLIT)               // 246 outputs per block
#define ROWS_PER_BLOCK (TPB + DSZ)      // 256 band rows per block
#define BAND_W 19                       // cols r+2 .. r+20
#define BAND_STRIDE 21                  // coprime with 32 -> conflict-free
#define W_STRIDE 11                     // coprime with 32 -> conflict-free

__global__ __launch_bounds__(256, 4)
void tad_insulation_kernel(const float* __restrict__ x, float* __restrict__ out) {
    const int b     = blockIdx.x;       // batch
    const int split = blockIdx.y;       // t-range half
    const int t0    = split * TPB;
    const float* __restrict__ xb = x + (size_t)b * MATSIZE * MATSIZE;

    __shared__ float band[ROWS_PER_BLOCK * BAND_STRIDE];  // 21504 B
    __shared__ float wsum[ROWS_PER_BLOCK * W_STRIDE];     // 11264 B

    const int tid  = threadIdx.x;
    const int lane = tid & 31;
    const int warp = tid >> 5;

    // ---- Phase 1: load diagonal band rows [t0, t0+255], cols r+2 .. r+20 ----
    // One row segment per warp-iteration; 19 active lanes touch 1-2 L2 sectors.
    // 32 independent predicated LDGs per thread -> deep MLP to cover DRAM latency.
    for (int lr = warp; lr < ROWS_PER_BLOCK; lr += 8) {
        const int r = t0 + lr;
        if (lane < BAND_W) {
            const int c = r + 2 + lane;
            float v = 0.0f;
            if (c < MATSIZE) v = xb[r * MATSIZE + c];
            band[lr * BAND_STRIDE + lane] = v;
        }
    }
    __syncthreads();

    // ---- Phase 2: per-row sliding window sums W[lr][k] = sum_{j<10} band[lr][k+j] ----
    {
        const float* bp = &band[tid * BAND_STRIDE];   // tid == lr, 256 threads = 256 rows
        float s = 0.0f;
        #pragma unroll
        for (int j = 0; j < DSZ; j++) s += bp[j];
        float* wp = &wsum[tid * W_STRIDE];
        wp[0] = s;
        #pragma unroll
        for (int k = 1; k < DSZ; k++) {
            s += bp[k + DSZ - 1] - bp[k - 1];
            wp[k] = s;
        }
    }
    __syncthreads();

    // ---- Phase 3: out[t] = (1/100) * sum_{i<10} W[t+i][9-i] ----
    if (tid < TPB) {
        float s = 0.0f;
        #pragma unroll
        for (int i = 0; i < DSZ; i++)
            s += wsum[(tid + i) * W_STRIDE + (DSZ - 1 - i)];
        out[b * NR + t0 + tid] = s * (1.0f / (DSZ * DSZ));
    }
}

extern "C" void kernel_launch(void* const* d_in, const int* in_sizes, int n_in,
                              void* d_out, int out_size) {
    (void)in_sizes; (void)n_in; (void)out_size;
    const float* x = (const float*)d_in[0];
    float* out = (float*)d_out;
    dim3 grid(256, TSPLIT);
    tad_insulation_kernel<<<grid, 256>>>(x, out);
}

// round 5
// speedup vs baseline: 1.4103x; 1.4103x over previous
#include <cuda_runtime.h>
#include <cuda_bf16.h>

#define MATSIZE 512
#define DSZ 10
#define NR (MATSIZE - 2 * DSZ)          // 492 outputs per batch
#define TSPLIT 2
#define TPB (NR / TSPLIT)               // 246 outputs per block
#define ROWS_PER_BLOCK (TPB + DSZ)      // 256 band rows per block
#define BSTRIDE 33                      // 32 floats stored + 1 pad -> conflict-free
#define W_STRIDE 11                     // coprime with 32 -> conflict-free
#define ROW_PITCH (MATSIZE + 1)         // diagonal pitch: idx(r, r+2+lane) = r*513 + 2 + lane

__global__ __launch_bounds__(256)
void tad_insulation_kernel(const float* __restrict__ x, float* __restrict__ out) {
    const int b     = blockIdx.x;       // batch
    const int split = blockIdx.y;       // t-range half
    const int t0    = split * TPB;

    __shared__ float band[ROWS_PER_BLOCK * BSTRIDE];   // 33792 B
    __shared__ float wsum[ROWS_PER_BLOCK * W_STRIDE];  // 11264 B

    const int tid  = threadIdx.x;
    const int lane = tid & 31;
    const int warp = tid >> 5;

    // ---- Phase 1: load diagonal band, rows r = t0+warp+8i (i=0..31), cols r+2+lane ----
    // All 32 loads issued back-to-back from one base pointer with immediate offsets
    // (batched BEFORE any STS) -> MLP = 32 per thread. All lanes load unconditionally:
    // every address provably stays inside the 256*512*512 allocation; lanes >= 19 land
    // in band columns that Phases 2-3 never read.
    {
        const float* __restrict__ p =
            x + (size_t)b * MATSIZE * MATSIZE
              + (size_t)(t0 + warp) * ROW_PITCH + 2 + lane;
        float v[32];
        #pragma unroll
        for (int i = 0; i < 32; i++)
            v[i] = p[(size_t)i * 8 * ROW_PITCH];     // compile-time immediate offsets
        #pragma unroll
        for (int i = 0; i < 32; i++)
            band[(warp + 8 * i) * BSTRIDE + lane] = v[i];
    }
    __syncthreads();

    // ---- Phase 2: per-row sliding window sums W[lr][k] = sum_{j<10} band[lr][k+j] ----
    {
        const float* bp = &band[tid * BSTRIDE];      // tid == local row, conflict-free
        float s = 0.0f;
        #pragma unroll
        for (int j = 0; j < DSZ; j++) s += bp[j];
        float* wp = &wsum[tid * W_STRIDE];
        wp[0] = s;
        #pragma unroll
        for (int k = 1; k < DSZ; k++) {
            s += bp[k + DSZ - 1] - bp[k - 1];
            wp[k] = s;
        }
    }
    __syncthreads();

    // ---- Phase 3: out[t] = (1/100) * sum_{i<10} W[t+i][9-i] ----
    if (tid < TPB) {
        float s = 0.0f;
        #pragma unroll
        for (int i = 0; i < DSZ; i++)
            s += wsum[(tid + i) * W_STRIDE + (DSZ - 1 - i)];
        out[b * NR + t0 + tid] = s * (1.0f / (DSZ * DSZ));
    }
}

extern "C" void kernel_launch(void* const* d_in, const int* in_sizes, int n_in,
                              void* d_out, int out_size) {
    (void)in_sizes; (void)n_in; (void)out_size;
    const float* x = (const float*)d_in[0];
    float* out = (float*)d_out;
    dim3 grid(256, TSPLIT);
    tad_insulation_kernel<<<grid, 256>>>(x, out);
}

// round 6
// speedup vs baseline: 1.4981x; 1.0623x over previous
#include <cuda_runtime.h>
#include <cuda_bf16.h>

#define MATSIZE 512
#define DSZ 10
#define NR (MATSIZE - 2 * DSZ)          // 492 outputs per batch
#define TSPLIT 2
#define TPB (NR / TSPLIT)               // 246 outputs per block
#define ROWS_PER_BLOCK (TPB + DSZ)      // 256 band rows per block
#define BAND_W 19                       // cols r+2 .. r+20 (all that is ever read)
#define BSTRIDE 21                      // 19 floats + pad, gcd(21,32)=1 -> conflict-free
#define W_STRIDE 11                     // coprime with 32 -> conflict-free
#define ROW_PITCH (MATSIZE + 1)         // diagonal pitch: idx(r, r+2+lane) = r*513 + 2 + lane

__global__ __launch_bounds__(256)
void tad_insulation_kernel(const float* __restrict__ x, float* __restrict__ out) {
    const int b     = blockIdx.x;       // batch
    const int split = blockIdx.y;       // t-range half
    const int t0    = split * TPB;

    __shared__ float band[ROWS_PER_BLOCK * BSTRIDE];   // 21504 B
    __shared__ float wsum[ROWS_PER_BLOCK * W_STRIDE];  // 11264 B

    const int tid  = threadIdx.x;
    const int lane = tid & 31;
    const int warp = tid >> 5;

    // ---- Phase 1: load diagonal band, rows r = t0+warp+8i (i=0..31), cols r+2+lane ----
    // 32 loads batched off ONE base pointer with compile-time immediate offsets,
    // all issued before any STS -> MLP = 32 per thread. Only the 19 useful lanes
    // load (loop-invariant predicate, batching preserved): a 76-byte span touches
    // ~1.53 128B lines/row vs 2.0 for a full 32-lane span -> ~21% less DRAM/L2
    // line traffic and ~32% fewer L2->L1 sectors. Addresses provably in-bounds
    // for the whole allocation (max index 257,033 < 262,144 per batch).
    {
        const bool active = (lane < BAND_W);
        const float* __restrict__ p =
            x + (size_t)b * MATSIZE * MATSIZE
              + (size_t)(t0 + warp) * ROW_PITCH + 2 + lane;
        float v[32];
        #pragma unroll
        for (int i = 0; i < 32; i++) {
            v[i] = 0.0f;
            if (active) v[i] = p[(size_t)i * 8 * ROW_PITCH];   // @P LDG, imm offsets
        }
        if (active) {
            #pragma unroll
            for (int i = 0; i < 32; i++)
                band[(warp + 8 * i) * BSTRIDE + lane] = v[i];
        }
    }
    __syncthreads();

    // ---- Phase 2: per-row sliding window sums W[lr][k] = sum_{j<10} band[lr][k+j] ----
    {
        const float* bp = &band[tid * BSTRIDE];      // tid == local row, conflict-free
        float s = 0.0f;
        #pragma unroll
        for (int j = 0; j < DSZ; j++) s += bp[j];
        float* wp = &wsum[tid * W_STRIDE];
        wp[0] = s;
        #pragma unroll
        for (int k = 1; k < DSZ; k++) {
            s += bp[k + DSZ - 1] - bp[k - 1];
            wp[k] = s;
        }
    }
    __syncthreads();

    // ---- Phase 3: out[t] = (1/100) * sum_{i<10} W[t+i][9-i] ----
    if (tid < TPB) {
        float s = 0.0f;
        #pragma unroll
        for (int i = 0; i < DSZ; i++)
            s += wsum[(tid + i) * W_STRIDE + (DSZ - 1 - i)];
        out[b * NR + t0 + tid] = s * (1.0f / (DSZ * DSZ));
    }
}

extern "C" void kernel_launch(void* const* d_in, const int* in_sizes, int n_in,
                              void* d_out, int out_size) {
    (void)in_sizes; (void)n_in; (void)out_size;
    const float* x = (const float*)d_in[0];
    float* out = (float*)d_out;
    dim3 grid(256, TSPLIT);
    tad_insulation_kernel<<<grid, 256>>>(x, out);
}

// round 8
// speedup vs baseline: 1.6886x; 1.1272x over previous
#include <cuda_runtime.h>
#include <cuda_bf16.h>

#define MATSIZE 512
#define DSZ 10
#define NR (MATSIZE - 2 * DSZ)          // 492 outputs per batch
#define TSPLIT 4
#define TPB (NR / TSPLIT)               // 123 outputs per block
#define ROWS_USED (TPB + DSZ)           // 133 band rows consumed per block
#define ROWS_PAD 136                    // 8 warps * 17 rows loaded (pad rows unused)
#define NLOAD 17                        // rows per thread, batched -> MLP = 17
#define BAND_W 19                       // cols r+2 .. r+20 (all that is ever read)
#define BSTRIDE 21                      // gcd(21,32)=1 -> conflict-free
#define W_STRIDE 11                     // gcd(11,32)=1 -> conflict-free
#define ROW_PITCH (MATSIZE + 1)         // idx(r, r+2+lane) = r*513 + 2 + lane

__global__ __launch_bounds__(256)
void tad_insulation_kernel(const float* __restrict__ x, float* __restrict__ out) {
    const int b     = blockIdx.x;       // batch
    const int split = blockIdx.y;       // t-range quarter
    const int t0    = split * TPB;

    __shared__ float band[ROWS_PAD * BSTRIDE];    // 11424 B
    __shared__ float wsum[ROWS_USED * W_STRIDE];  //  5852 B

    const int tid  = threadIdx.x;
    const int lane = tid & 31;
    const int warp = tid >> 5;

    // ---- Phase 1: load diagonal band rows r = t0+warp+8i (i=0..16), cols r+2+lane ----
    // 17 loads batched off ONE base pointer with compile-time immediate offsets,
    // all issued before any STS -> MLP = 17 per thread, with 2x the thread count
    // of the previous version (8192 warps total -> ~75-85% occupancy).
    // Only the 19 useful lanes participate. All addresses provably in-bounds:
    // max r = 369+7+128 = 504, max idx = 504*513 + 20 = 258,572 < 262,144/batch.
    {
        const bool active = (lane < BAND_W);
        const float* __restrict__ p =
            x + (size_t)b * MATSIZE * MATSIZE
              + (size_t)(t0 + warp) * ROW_PITCH + 2 + lane;
        if (active) {
            float v[NLOAD];
            #pragma unroll
            for (int i = 0; i < NLOAD; i++)
                v[i] = p[(size_t)i * 8 * ROW_PITCH];     // imm offsets, back-to-back LDG
            #pragma unroll
            for (int i = 0; i < NLOAD; i++)
                band[(warp + 8 * i) * BSTRIDE + lane] = v[i];
        }
    }
    __syncthreads();

    // ---- Phase 2: per-row sliding window sums W[lr][k] = sum_{j<10} band[lr][k+j] ----
    if (tid < ROWS_USED) {
        const float* bp = &band[tid * BSTRIDE];      // conflict-free (stride 21)
        float s = 0.0f;
        #pragma unroll
        for (int j = 0; j < DSZ; j++) s += bp[j];
        float* wp = &wsum[tid * W_STRIDE];
        wp[0] = s;
        #pragma unroll
        for (int k = 1; k < DSZ; k++) {
            s += bp[k + DSZ - 1] - bp[k - 1];
            wp[k] = s;
        }
    }
    __syncthreads();

    // ---- Phase 3: out[t] = (1/100) * sum_{i<10} W[t+i][9-i] ----
    if (tid < TPB) {
        float s = 0.0f;
        #pragma unroll
        for (int i = 0; i < DSZ; i++)
            s += wsum[(tid + i) * W_STRIDE + (DSZ - 1 - i)];
        out[b * NR + t0 + tid] = s * (1.0f / (DSZ * DSZ));
    }
}

extern "C" void kernel_launch(void* const* d_in, const int* in_sizes, int n_in,
                              void* d_out, int out_size) {
    (void)in_sizes; (void)n_in; (void)out_size;
    const float* x = (const float*)d_in[0];
    float* out = (float*)d_out;
    dim3 grid(256, TSPLIT);
    tad_insulation_kernel<<<grid, 256>>>(x, out);
}